// round 7
// baseline (speedup 1.0000x reference)
#include <cuda_runtime.h>
#include <cuda_bf16.h>

// Wav2Frames: out[b, c, f] = x[b, f*WINSTEP + c]
// x: (32, 1, 480000) fp32 -> out: (32, 400, 2998) fp32
//
// R7: c-quarter tiling for 2x longer DRAM write runs.
//   CTA = (batch, c-quarter of 100 cols, frame tile of 256).
//   Since 100 < WINSTEP, only the per-frame 100-float windows are staged
//   (compact frame-major smem, pitch 101), so 256+6 frames fit in ~106 KB
//   -> still 2 CTAs/SM. Per-row write chunks double to 1KB, kept
//   sector-aligned with the R6 shift s(c) = (2c)&7.
//   Quarters of one tile are adjacent blockIdx -> x reuse (<=3x) hits L2;
//   compulsory DRAM reads stay 61.5 MB.

#define B        32
#define T        480000
#define WINLEN   400
#define WINSTEP  160
#define NFRAMES  2998
#define F_TILE   256
#define NTILES   12                       // 12*256 = 3072 >= 2998+6
#define CW       100                      // columns per quarter
#define PITCH    101                      // odd -> conflict-free fill STS
#define NFR_SM   (F_TILE + 6)             // shift room (s <= 6)
#define SM_SZ    (NFR_SM * PITCH)         // 26462 floats (~105.8 KB)
#define THREADS  1024

__global__ __launch_bounds__(THREADS, 2)
void wav2frames_kernel(const float* __restrict__ x, float* __restrict__ out) {
    extern __shared__ float sm[];

    const int tile = blockIdx.x >> 2;     // frame tile 0..11
    const int qtr  = blockIdx.x & 3;      // c-quarter 0..3
    const int b    = blockIdx.y;
    const int tid  = threadIdx.x;
    const int lane = tid & 31;
    const int w    = tid >> 5;            // 32 warps

    const int c0 = qtr * CW;
    const int f0 = tile * F_TILE;

    // ---- fill: per-frame 100-float windows -> compact frame-major smem ----
    // scalar LDG (coalesced within each 400B window) + conflict-free STS.32
    const int fmax = (NFRAMES - f0 < NFR_SM) ? (NFRAMES - f0) : NFR_SM;
    const float* __restrict__ xb = x + (size_t)b * T + (size_t)f0 * WINSTEP + c0;

    const int nelem = fmax * CW;
    for (int idx = tid; idx < nelem; idx += THREADS) {   // <= 26 iters
        const int fidx = idx / CW;
        const int cc   = idx - fidx * CW;
        sm[fidx * PITCH + cc] = xb[fidx * WINSTEP + cc];
    }
    __syncthreads();

    float* __restrict__ outb = out + (size_t)b * WINLEN * NFRAMES;

    // ---- drain: 128 frame pairs x 8 c-groups, shift s(c) for alignment ----
    const int q  = w & 3;                 // pair block 0..3
    const int cg = w >> 2;                // c-group 0..7
    const int pi = lane + 32 * q;         // pair index 0..127
    const int fb = f0 + 2 * pi;           // even frame base (no shift)
    const int jb = 2 * pi * PITCH;

    #pragma unroll 4
    for (int c = cg; c < CW; c += 8) {    // 12-13 iterations
        const int s = (2 * c) & 7;        // (2*(c0+c))&7 since 2*c0 % 8 == 0
        const int f = fb + s;
        if (f <= NFRAMES - 2) {
            const int j0 = jb + s * PITCH + c;
            float2 v;
            v.x = sm[j0];
            v.y = sm[j0 + PITCH];
            *reinterpret_cast<float2*>(outb + (size_t)(c0 + c) * NFRAMES + f) = v;
        }
    }

    // ---- head: tile 0 writes frames [0, s(c)) for each of its rows ----
    if (tile == 0) {
        for (int idx = tid; idx < CW * 3; idx += THREADS) {
            const int c = idx / 3;
            const int m = idx - 3 * c;    // pair slot 0..2
            const int s = (2 * c) & 7;
            if (2 * m < s) {
                const int j0 = (2 * m) * PITCH + c;
                float2 v;
                v.x = sm[j0];
                v.y = sm[j0 + PITCH];
                *reinterpret_cast<float2*>(
                    outb + (size_t)(c0 + c) * NFRAMES + 2 * m) = v;
            }
        }
    }
}

extern "C" void kernel_launch(void* const* d_in, const int* in_sizes, int n_in,
                              void* d_out, int out_size) {
    const float* x = (const float*)d_in[0];            // (32, 1, 480000) fp32
    // d_in[1] = W (identity, unused), d_in[2] = winstep (fixed 160, unused)
    float* out = (float*)d_out;                        // (32, 400, 2998) fp32

    static bool configured = false;
    if (!configured) {
        cudaFuncSetAttribute(wav2frames_kernel,
                             cudaFuncAttributeMaxDynamicSharedMemorySize,
                             SM_SZ * (int)sizeof(float));
        configured = true;
    }

    dim3 grid(NTILES * 4, B);                          // 48 x 32 = 1536 CTAs
    wav2frames_kernel<<<grid, THREADS, SM_SZ * sizeof(float)>>>(x, out);
}

// round 8
// speedup vs baseline: 1.3506x; 1.3506x over previous
#include <cuda_runtime.h>
#include <cuda_bf16.h>

// Wav2Frames: out[b, c, f] = x[b, f*WINSTEP + c]
// x: (32, 1, 480000) fp32 -> out: (32, 400, 2998) fp32
//
// R8: residue-group tiling.
//   Rows c, c+160, c+320 share the residue stream x[g*160 + (c%160)].
//   CTA = (b, residue group r0 (32 residues), frame chunk of 752):
//     stage X[rr][g] = x[g*160 + r0 + rr]  (g in [fq, fq+760), 95KB smem)
//     out[c = r0+rr+160m][f] = X[rr][f+m-fq]
//   -> write runs of 3KB/row (6x R6), reads happen exactly once globally
//      at 100% sector efficiency. Per-row shift s(c)=(2c)&7 keeps every
//      run 32B-aligned (R6's confirmed win). Streaming cache hints.

#define B        32
#define T        480000
#define WINLEN   400
#define WINSTEP  160
#define NFRAMES  2998
#define FCHUNK   752                      // multiple of 16; 4*752 >= 2998+6
#define NCHUNK   4
#define NRG      5                        // residue groups of 32 (5*32=160)
#define GSPAN    760                      // frames staged: 752 + s(6) + m(2)
#define PITCH    761                      // odd pitch
#define SM_FLOATS (32 * PITCH)            // 24352 floats = 95.1 KB
#define THREADS  1024

__global__ __launch_bounds__(THREADS, 2)
void wav2frames_kernel(const float* __restrict__ x, float* __restrict__ out) {
    extern __shared__ float X[];          // X[rr * PITCH + g_local]

    const int q  = blockIdx.x & 3;        // frame chunk 0..3
    const int rg = blockIdx.x >> 2;       // residue group 0..4
    const int b  = blockIdx.y;
    const int r0 = rg * 32;
    const int fq = q * FCHUNK;

    const int tid  = threadIdx.x;
    const int lane = tid & 31;
    const int w    = tid >> 5;            // 32 warps

    // ---- fill: X[4t+i][gl] = x[(fq+gl)*160 + r0 + 4t + i] via float4 LDG ----
    // warp: 4 g's x 8 lanes -> 4 x 128B contiguous reads (full sectors).
    // STS banks: ((4t+i)*761 + gl) mod 32 = (4t + 25i + gl) mod 32,
    // distinct over (t, gl&3) per instruction i -> conflict-free.
    const float* __restrict__ xb = x + (size_t)b * T;
    for (int idx = tid; idx < GSPAN * 8; idx += THREADS) {   // 6 iterations
        const int gl = idx >> 3;
        const int t  = idx & 7;
        const int xi = (fq + gl) * WINSTEP + r0 + 4 * t;
        if (xi + 3 < T) {
            const float4 v = __ldcs(reinterpret_cast<const float4*>(xb + xi));
            float* dst = X + (4 * t) * PITCH + gl;
            dst[0 * PITCH] = v.x;
            dst[1 * PITCH] = v.y;
            dst[2 * PITCH] = v.z;
            dst[3 * PITCH] = v.w;
        }
    }
    __syncthreads();

    // ---- drain: rows (m, rr); 3KB contiguous run per row, shift s(c) ----
    const int lim   = 80 - r0;                           // m=2 valid rr count
    const int m2    = lim < 0 ? 0 : (lim > 32 ? 32 : lim);
    const int nrows = 64 + m2;                           // 64..96

    float* __restrict__ outb = out + (size_t)b * WINLEN * NFRAMES;

    for (int ri = w; ri < nrows; ri += 32) {             // <= 3 rows per warp
        const int m  = ri >> 5;
        const int rr = ri & 31;
        const int c  = r0 + rr + 160 * m;
        const int s  = (2 * c) & 7;                      // even, 0..6
        const int fstart = fq + s;                       // 32B-aligned start
        int fend = fq + FCHUNK + s;
        if (fend > NFRAMES) fend = NFRAMES;
        const int cnt = fend - fstart;                   // always even

        const float* __restrict__ Xr = X + rr * PITCH + s + m;
        float* __restrict__ orow = outb + (size_t)c * NFRAMES;

        // head frames [0, s) written by chunk 0 (g_local = f + m)
        if (q == 0 && 2 * lane < s) {
            const float* Xh = X + rr * PITCH + m + 2 * lane;
            float2 h;
            h.x = Xh[0];
            h.y = Xh[1];
            __stcs(reinterpret_cast<float2*>(orow + 2 * lane), h);
        }

        #pragma unroll 4
        for (int fo = 2 * lane; fo < cnt; fo += 64) {    // 12 iterations
            float2 v;
            v.x = Xr[fo];                                // 2-way LDS, proven ok
            v.y = Xr[fo + 1];
            __stcs(reinterpret_cast<float2*>(orow + fstart + fo), v);
        }
    }
}

extern "C" void kernel_launch(void* const* d_in, const int* in_sizes, int n_in,
                              void* d_out, int out_size) {
    const float* x = (const float*)d_in[0];              // (32, 1, 480000) fp32
    // d_in[1] = W (identity, unused), d_in[2] = winstep (fixed 160, unused)
    float* out = (float*)d_out;                          // (32, 400, 2998) fp32

    static bool configured = false;
    if (!configured) {
        cudaFuncSetAttribute(wav2frames_kernel,
                             cudaFuncAttributeMaxDynamicSharedMemorySize,
                             SM_FLOATS * (int)sizeof(float));
        configured = true;
    }

    dim3 grid(NCHUNK * NRG, B);                          // 20 x 32 = 640 CTAs
    wav2frames_kernel<<<grid, THREADS, SM_FLOATS * sizeof(float)>>>(x, out);
}

// round 9
// speedup vs baseline: 1.3894x; 1.0287x over previous
#include <cuda_runtime.h>
#include <cuda_bf16.h>

// Wav2Frames: out[b, c, f] = x[b, f*WINSTEP + c]
// x: (32, 1, 480000) fp32 -> out: (32, 400, 2998) fp32
//
// R9 = R6 (best: 35.7us) + write-stream refinements only:
//  - per-row shift upgraded s(c) = (10c)&31: solves 88c + 4s == 0 (mod 128),
//    so every 512B row chunk is exactly 4 FULL 128B L2 lines (R6's (2c)&7
//    only gave 32B sector alignment; chunks straddled 5 lines, 2 partial).
//  - __ldcs / __stcs streaming hints: both streams are touch-once.
//  Everything else identical to R6: F_TILE=128, 1024 thr, 2 CTAs/SM,
//  float4 LDG fill, skew j+(j>>5), float2 frame-pair STG.

#define B        32
#define T        480000
#define WINLEN   400
#define WINSTEP  160
#define NFRAMES  2998
#define F_TILE   128
#define NTILES   24                                    // 24*128 = 3072 >= 2998
#define SPAN     ((F_TILE - 1) * WINSTEP + WINLEN + 30 * WINSTEP)  // 25520
#define SM_SZ    (SPAN + SPAN / 32 + 4)                // 26321 floats (~105.3 KB)
#define THREADS  1024

__global__ __launch_bounds__(THREADS, 2)
void wav2frames_kernel(const float* __restrict__ x, float* __restrict__ out) {
    extern __shared__ float sm[];

    const int tile = blockIdx.x;
    const int b    = blockIdx.y;
    const int tid  = threadIdx.x;
    const int lane = tid & 31;
    const int w    = tid >> 5;                         // 32 warps

    const int f0 = tile * F_TILE;                      // multiple of 128
    const int x0 = f0 * WINSTEP;

    // ---- vectorized coalesced fill: gmem float4 -> skewed smem ----
    const float* __restrict__ xb = x + (size_t)b * T + x0;
    const int span  = (x0 + SPAN <= T) ? SPAN : (T - x0);   // multiple of 4
    const int span4 = span >> 2;
    const float4* __restrict__ xb4 = reinterpret_cast<const float4*>(xb);

    for (int i4 = tid; i4 < span4; i4 += THREADS) {    // ~7 iterations
        const float4 v = __ldcs(xb4 + i4);
        const int i = i4 << 2;
        const int p = i + (i >> 5);                    // skew: j + (j>>5)
        sm[p + 0] = v.x;
        sm[p + 1] = v.y;
        sm[p + 2] = v.z;
        sm[p + 3] = v.w;
    }
    __syncthreads();

    float* __restrict__ outb = out + (size_t)b * WINLEN * NFRAMES;

    // ---- main store: 64 frame pairs x 16 c-groups, 128B-aligned chunks ----
    const int q      = w & 1;
    const int cg     = w >> 1;                         // 0..15
    const int fp_idx = lane + 32 * q;                  // 0..63
    const int fbase  = f0 + 2 * fp_idx;                // even
    const int jbase  = 2 * fp_idx * WINSTEP;           // 320 * fp_idx

    #pragma unroll 5
    for (int c = cg; c < WINLEN; c += 16) {            // 25 iterations
        const int s = (10 * c) & 31;                   // even, 0..30
        const int f = fbase + s;
        if (f <= NFRAMES - 2) {
            const int j0 = jbase + s * WINSTEP + c;
            const int j1 = j0 + WINSTEP;
            float2 v;
            v.x = sm[j0 + (j0 >> 5)];
            v.y = sm[j1 + (j1 >> 5)];
            __stcs(reinterpret_cast<float2*>(outb + (size_t)c * NFRAMES + f), v);
        }
    }

    // ---- head: tile 0 writes frames [0, s(c)) for each row c ----
    if (tile == 0) {
        for (int idx = tid; idx < WINLEN * 15; idx += THREADS) {  // 6 iters
            const int c = idx / 15;
            const int m = idx - 15 * c;                // pair slot 0..14
            const int s = (10 * c) & 31;
            if (2 * m < s) {
                const int fh = 2 * m;
                const int j0 = fh * WINSTEP + c;
                const int j1 = j0 + WINSTEP;
                float2 v;
                v.x = sm[j0 + (j0 >> 5)];
                v.y = sm[j1 + (j1 >> 5)];
                __stcs(reinterpret_cast<float2*>(
                           outb + (size_t)c * NFRAMES + fh), v);
            }
        }
    }
}

extern "C" void kernel_launch(void* const* d_in, const int* in_sizes, int n_in,
                              void* d_out, int out_size) {
    const float* x = (const float*)d_in[0];            // (32, 1, 480000) fp32
    // d_in[1] = W (identity, unused), d_in[2] = winstep (fixed 160, unused)
    float* out = (float*)d_out;                        // (32, 400, 2998) fp32

    static bool configured = false;
    if (!configured) {
        cudaFuncSetAttribute(wav2frames_kernel,
                             cudaFuncAttributeMaxDynamicSharedMemorySize,
                             SM_SZ * (int)sizeof(float));
        configured = true;
    }

    dim3 grid(NTILES, B);                              // 24 x 32 = 768 CTAs
    wav2frames_kernel<<<grid, THREADS, SM_SZ * sizeof(float)>>>(x, out);
}

// round 10
// speedup vs baseline: 1.5736x; 1.1326x over previous
#include <cuda_runtime.h>
#include <cuda_bf16.h>

// Wav2Frames: out[b, c, f] = x[b, f*WINSTEP + c]
// x: (32, 1, 480000) fp32 -> out: (32, 400, 2998) fp32
//
// R10 = R6 verbatim, with the tile count tuned to the 296 concurrent-CTA
// slots (2 CTAs/SM x 148 SMs):
//   R6:  768 jobs = 2.59 x 296 -> makespan 3 rounds -> 86.5% slot efficiency
//   R10: F_TILE=112, NTILES=27 -> 864 jobs = 2.92 x 296 -> 97.3% efficiency
// Everything else identical: float4 LDG fill, smem skew j+(j>>5),
// per-row sector shift s(c)=(2c)&7 (the confirmed RMW win), float2
// frame-pair stores, 1024 threads, 2 CTAs/SM.

#define B        32
#define T        480000
#define WINLEN   400
#define WINSTEP  160
#define NFRAMES  2998
#define F_TILE   112
#define NTILES   27                                    // 27*112 = 3024 >= 2998
#define NPAIRS_T (F_TILE / 2)                          // 56 frame pairs
#define SPAN     ((F_TILE - 1) * WINSTEP + WINLEN + 6 * WINSTEP)  // 19120
#define SM_SZ    (SPAN + SPAN / 32 + 4)                // 19721 floats (~78.9 KB)
#define THREADS  1024

__global__ __launch_bounds__(THREADS, 2)
void wav2frames_kernel(const float* __restrict__ x, float* __restrict__ out) {
    extern __shared__ float sm[];

    const int tile = blockIdx.x;
    const int b    = blockIdx.y;
    const int tid  = threadIdx.x;
    const int lane = tid & 31;
    const int w    = tid >> 5;                         // 32 warps

    const int f0 = tile * F_TILE;                      // even
    const int x0 = f0 * WINSTEP;

    // ---- vectorized coalesced fill: gmem float4 -> skewed smem ----
    const float* __restrict__ xb = x + (size_t)b * T + x0;
    const int span  = (x0 + SPAN <= T) ? SPAN : (T - x0);   // multiple of 4
    const int span4 = span >> 2;
    const float4* __restrict__ xb4 = reinterpret_cast<const float4*>(xb);

    for (int i4 = tid; i4 < span4; i4 += THREADS) {    // ~5 iterations
        const float4 v = xb4[i4];
        const int i = i4 << 2;
        const int p = i + (i >> 5);                    // skew: j + (j>>5)
        sm[p + 0] = v.x;
        sm[p + 1] = v.y;
        sm[p + 2] = v.z;
        sm[p + 3] = v.w;
    }
    __syncthreads();

    float* __restrict__ outb = out + (size_t)b * WINLEN * NFRAMES;

    // ---- main store: 56 frame pairs x 16 c-groups, sector-aligned chunks ----
    const int q      = w & 1;
    const int cg     = w >> 1;                         // 0..15
    const int fp_idx = lane + 32 * q;                  // 0..63 (>=56 idle)
    const int fbase  = f0 + 2 * fp_idx;                // even
    const int jbase  = 2 * fp_idx * WINSTEP;           // 320 * fp_idx

    if (fp_idx < NPAIRS_T) {
        #pragma unroll 5
        for (int c = cg; c < WINLEN; c += 16) {        // 25 iterations
            const int s = (2 * c) & 7;                 // 0,2,4,6 (even)
            const int f = fbase + s;
            if (f <= NFRAMES - 2) {
                const int j0 = jbase + s * WINSTEP + c;
                const int j1 = j0 + WINSTEP;
                float2 v;
                v.x = sm[j0 + (j0 >> 5)];
                v.y = sm[j1 + (j1 >> 5)];
                *reinterpret_cast<float2*>(outb + (size_t)c * NFRAMES + f) = v;
            }
        }
    }

    // ---- head: tile 0 writes frames [0, s(c)) for each row c ----
    if (tile == 0) {
        for (int idx = tid; idx < WINLEN * 3; idx += THREADS) {
            const int c = idx / 3;
            const int m = idx - 3 * c;                 // pair slot 0..2
            const int s = (2 * c) & 7;
            if (2 * m < s) {
                const int fh = 2 * m;
                const int j0 = fh * WINSTEP + c;
                const int j1 = j0 + WINSTEP;
                float2 v;
                v.x = sm[j0 + (j0 >> 5)];
                v.y = sm[j1 + (j1 >> 5)];
                *reinterpret_cast<float2*>(outb + (size_t)c * NFRAMES + fh) = v;
            }
        }
    }
}

extern "C" void kernel_launch(void* const* d_in, const int* in_sizes, int n_in,
                              void* d_out, int out_size) {
    const float* x = (const float*)d_in[0];            // (32, 1, 480000) fp32
    // d_in[1] = W (identity, unused), d_in[2] = winstep (fixed 160, unused)
    float* out = (float*)d_out;                        // (32, 400, 2998) fp32

    static bool configured = false;
    if (!configured) {
        cudaFuncSetAttribute(wav2frames_kernel,
                             cudaFuncAttributeMaxDynamicSharedMemorySize,
                             SM_SZ * (int)sizeof(float));
        configured = true;
    }

    dim3 grid(NTILES, B);                              // 27 x 32 = 864 CTAs
    wav2frames_kernel<<<grid, THREADS, SM_SZ * sizeof(float)>>>(x, out);
}